// round 2
// baseline (speedup 1.0000x reference)
#include <cuda_runtime.h>
#include <cstdint>

#define BATCH 1024
#define INF   512
#define OUTF  512
#define BT    64
#define OT    64
#define KT    16
#define NSTAGES (INF / KT)   // 32
#define NPAIR  (OUTF / 2)    // 256 o-pairs

typedef unsigned long long ull;

// ---- f32x2 packed-math helpers (SASS FFMA2/FMUL2 — ptxas won't auto-fuse) ----
__device__ __forceinline__ ull fma2(ull a, ull b, ull c) {
    ull d; asm("fma.rn.f32x2 %0, %1, %2, %3;" : "=l"(d) : "l"(a), "l"(b), "l"(c)); return d;
}
__device__ __forceinline__ ull mul2(ull a, ull b) {
    ull d; asm("mul.rn.f32x2 %0, %1, %2;" : "=l"(d) : "l"(a), "l"(b)); return d;
}
__device__ __forceinline__ ull pk(float lo, float hi) {
    ull r; asm("mov.b64 %0, {%1, %2};" : "=l"(r) : "f"(lo), "f"(hi)); return r;
}
__device__ __forceinline__ void upk(float& lo, float& hi, ull v) {
    asm("mov.b64 {%0, %1}, %2;" : "=f"(lo), "=f"(hi) : "l"(v));
}
__device__ __forceinline__ float ex2neg(float q) {  // 2^(-q), sign flip on ALU pipe
    float r, qn = __int_as_float(__float_as_int(q) ^ 0x80000000);
    asm("ex2.approx.ftz.f32 %0, %1;" : "=f"(r) : "f"(qn));
    return r;
}

// Scratch (static __device__ globals: allocation-free per harness rules)
// Param entry per (o-pair, i): 32B = {inv0,inv1},{ty0,ty1},{wz0,wz1},{wb0,wb1}
// where inv = sqrt(ln2/2)/s, ty = -t*inv  (so w = x*inv+ty gives ex2 arg = -w^2)
__device__ ulonglong2 g_P2[NPAIR * INF * 2];
__device__ float      g_Xx[INF * BATCH];    // x transposed [i][b]
__device__ float      g_Xs[INF * BATCH];    // silu(x) transposed [i][b]

// ---------------------------------------------------------------------------
// Prep 1: pack per-(o-pair,i) params. Reads coalesced (i fast), writes 32B/thread.
// ---------------------------------------------------------------------------
__global__ void prep_params(const float* __restrict__ bw, const float* __restrict__ ww,
                            const float* __restrict__ sc, const float* __restrict__ tr) {
    int idx = blockIdx.x * blockDim.x + threadIdx.x;
    if (idx >= NPAIR * INF) return;
    int i  = idx & (INF - 1);
    int op = idx >> 9;
    int o0 = 2 * op;
    const float K = 0.84936056542f;              // sqrt(ln2/2) = sqrt(0.72134752)
    float inv0 = K * __frcp_rn(sc[(size_t)o0 * INF + i]);
    float inv1 = K * __frcp_rn(sc[(size_t)(o0 + 1) * INF + i]);
    float ty0  = -tr[(size_t)o0 * INF + i] * inv0;
    float ty1  = -tr[(size_t)(o0 + 1) * INF + i] * inv1;
    float wz0  = ww[(size_t)o0 * INF + i];
    float wz1  = ww[(size_t)(o0 + 1) * INF + i];
    float wb0  = bw[(size_t)o0 * INF + i];
    float wb1  = bw[(size_t)(o0 + 1) * INF + i];
    ulonglong2 e0, e1;
    e0.x = pk(inv0, inv1); e0.y = pk(ty0, ty1);
    e1.x = pk(wz0, wz1);   e1.y = pk(wb0, wb1);
    size_t base = (size_t)idx * 2;               // [op][i] entry order
    g_P2[base]     = e0;
    g_P2[base + 1] = e1;
}

// ---------------------------------------------------------------------------
// Prep 2: transpose x to [i][b] and precompute silu(x)
// ---------------------------------------------------------------------------
__global__ void prep_x(const float* __restrict__ x) {
    int idx = blockIdx.x * blockDim.x + threadIdx.x;
    if (idx >= INF * BATCH) return;
    int i = idx / BATCH;
    int b = idx % BATCH;
    float v = x[(size_t)b * INF + i];
    float e = __expf(-v);
    g_Xx[idx] = v;
    g_Xs[idx] = v / (1.0f + e);
}

// ---------------------------------------------------------------------------
// Main: 64x64 (b,o) tile, 256 threads, 4b x 2 o-pair micro-tile, f32x2 math.
// ---------------------------------------------------------------------------
__global__ void __launch_bounds__(256)
wkan_main(const float* __restrict__ bias, float* __restrict__ out) {
    // Param tile: entry (k, op) = 2x ulonglong2 at [k][2*op], [k][2*op+1]
    __shared__ ulonglong2 sP[2][KT][2 * (OT / 2)];   // 32 KB
    __shared__ float4     sX[2][KT][BT / 4];         //  8 KB
    __shared__ float4     sS[2][KT][BT / 4];         //  8 KB  -> 48 KB

    const int tid = threadIdx.x;
    const int tb  = tid & 15;        // 16 batch groups (4 b each)
    const int to  = tid >> 4;        // 16 o-pair groups (2 pairs each)
    const int b0  = blockIdx.x * BT;
    const int o0  = blockIdx.y * OT;
    const int op0 = o0 / 2;

    auto load_stage = [&](int s, int buf) {
        const int k0 = s * KT;
        // ---- param tile: 1024 x 16B chunks; warp covers ops at fixed k -> STS conflict-free
        #pragma unroll
        for (int j = 0; j < 4; ++j) {
            int idx  = j * 256 + tid;
            int k    = idx >> 6;            // 0..15
            int c    = idx & 63;            // op*2 + half
            int op   = c >> 1;
            int half = c & 1;
            const ulonglong2* src = &g_P2[((size_t)(op0 + op) * INF + (k0 + k)) * 2 + half];
            uint32_t dst = (uint32_t)__cvta_generic_to_shared(&sP[buf][k][c]);
            asm volatile("cp.async.cg.shared.global [%0], [%1], 16;\n" :: "r"(dst), "l"(src));
        }
        // ---- x / silu tiles: 256 float4 each, 1 per thread
        {
            int k  = tid >> 4;
            int b4 = tid & 15;
            const float* srcx = &g_Xx[(size_t)(k0 + k) * BATCH + b0 + b4 * 4];
            uint32_t dstx = (uint32_t)__cvta_generic_to_shared(&sX[buf][k][b4]);
            asm volatile("cp.async.cg.shared.global [%0], [%1], 16;\n" :: "r"(dstx), "l"(srcx));
            const float* srcs = &g_Xs[(size_t)(k0 + k) * BATCH + b0 + b4 * 4];
            uint32_t dsts = (uint32_t)__cvta_generic_to_shared(&sS[buf][k][b4]);
            asm volatile("cp.async.cg.shared.global [%0], [%1], 16;\n" :: "r"(dsts), "l"(srcs));
        }
        asm volatile("cp.async.commit_group;\n" ::);
    };

    const ull C2 = pk(1.38629436112f, 1.38629436112f);   // 2*ln2 = 1/0.72134752
    const ull M1 = pk(-1.0f, -1.0f);

    ull acc[4][2];
    #pragma unroll
    for (int i = 0; i < 4; ++i) { acc[i][0] = 0ull; acc[i][1] = 0ull; }

    load_stage(0, 0);
    load_stage(1, 1);

    #pragma unroll 1
    for (int s = 0; s < NSTAGES; ++s) {
        asm volatile("cp.async.wait_group 1;\n" ::);
        __syncthreads();
        const int buf = s & 1;

        #pragma unroll 8
        for (int k = 0; k < KT; ++k) {
            float4 xa = sX[buf][k][tb];
            float4 xs = sS[buf][k][tb];
            ull xx[4] = { pk(xa.x, xa.x), pk(xa.y, xa.y), pk(xa.z, xa.z), pk(xa.w, xa.w) };
            ull ss[4] = { pk(xs.x, xs.x), pk(xs.y, xs.y), pk(xs.z, xs.z), pk(xs.w, xs.w) };
            #pragma unroll
            for (int oo = 0; oo < 2; ++oo) {
                int c = 2 * (2 * to + oo);
                ulonglong2 pa = sP[buf][k][c];       // {inv01, ty01}
                ulonglong2 pb = sP[buf][k][c + 1];   // {wz01,  wb01}
                #pragma unroll
                for (int bb = 0; bb < 4; ++bb) {
                    ull w  = fma2(xx[bb], pa.x, pa.y);   // w = k*(x-t)/s  (pair of o)
                    ull q  = mul2(w, w);                 // q = ln2/2 * u^2
                    float qa, qb; upk(qa, qb, q);
                    float ea = ex2neg(qa);               // exp(-u^2/2)
                    float eb = ex2neg(qb);
                    ull e2   = pk(ea, eb);
                    ull u2m1 = fma2(q, C2, M1);          // u^2 - 1
                    ull t    = mul2(u2m1, e2);
                    acc[bb][oo] = fma2(t, pb.x, acc[bb][oo]);       // wavelet
                    acc[bb][oo] = fma2(ss[bb], pb.y, acc[bb][oo]);  // base (fused)
                }
            }
        }
        __syncthreads();
        if (s + 2 < NSTAGES) load_stage(s + 2, buf);
        else                 asm volatile("cp.async.commit_group;\n" ::);
    }

    // Epilogue: thread covers o = o0 + 4*to .. 4*to+3 (two pairs) for 4 b rows
    float4 bv = *reinterpret_cast<const float4*>(bias + o0 + 4 * to);
    #pragma unroll
    for (int bb = 0; bb < 4; ++bb) {
        int b = b0 + 4 * tb + bb;
        float a0, a1, a2, a3;
        upk(a0, a1, acc[bb][0]);
        upk(a2, a3, acc[bb][1]);
        float4 r;
        r.x = a0 + bv.x; r.y = a1 + bv.y; r.z = a2 + bv.z; r.w = a3 + bv.w;
        *reinterpret_cast<float4*>(out + (size_t)b * OUTF + o0 + 4 * to) = r;
    }
}

// ---------------------------------------------------------------------------
extern "C" void kernel_launch(void* const* d_in, const int* in_sizes, int n_in,
                              void* d_out, int out_size) {
    (void)in_sizes; (void)n_in; (void)out_size;
    const float* x    = (const float*)d_in[0];
    const float* bw   = (const float*)d_in[1];
    const float* ww   = (const float*)d_in[2];
    const float* sc   = (const float*)d_in[3];
    const float* tr   = (const float*)d_in[4];
    const float* bias = (const float*)d_in[5];
    float* out = (float*)d_out;

    prep_params<<<(NPAIR * INF + 255) / 256, 256>>>(bw, ww, sc, tr);
    prep_x<<<(INF * BATCH + 255) / 256, 256>>>(x);
    wkan_main<<<dim3(BATCH / BT, OUTF / OT), 256>>>(bias, out);
}

// round 3
// speedup vs baseline: 1.1439x; 1.1439x over previous
#include <cuda_runtime.h>
#include <cstdint>

#define BATCH 1024
#define INF   512
#define OUTF  512
#define BT    64
#define OT    64
#define KT    16
#define NSTAGES (INF / KT)   // 32

typedef unsigned long long ull;

// ---- f32x2 packed-math helpers ----
__device__ __forceinline__ ull fma2(ull a, ull b, ull c) {
    ull d; asm("fma.rn.f32x2 %0, %1, %2, %3;" : "=l"(d) : "l"(a), "l"(b), "l"(c)); return d;
}
__device__ __forceinline__ ull mul2(ull a, ull b) {
    ull d; asm("mul.rn.f32x2 %0, %1, %2;" : "=l"(d) : "l"(a), "l"(b)); return d;
}
__device__ __forceinline__ ull xor64(ull a, ull m) {
    ull d; asm("xor.b64 %0, %1, %2;" : "=l"(d) : "l"(a), "l"(m)); return d;
}
__device__ __forceinline__ ull pk(float lo, float hi) {
    ull r; asm("mov.b64 %0, {%1, %2};" : "=l"(r) : "f"(lo), "f"(hi)); return r;
}
__device__ __forceinline__ void upk(float& lo, float& hi, ull v) {
    asm("mov.b64 {%0, %1}, %2;" : "=f"(lo), "=f"(hi) : "l"(v));
}
__device__ __forceinline__ float ex2f(float q) {
    float r; asm("ex2.approx.ftz.f32 %0, %1;" : "=f"(r) : "f"(q)); return r;
}

// Scratch (static __device__ globals: allocation-free per harness rules)
// Param per (o,i): float4 {inv = K/s, ty = -K*t/s, wz, wb}, K = sqrt(ln2/2)
// so w = x*inv+ty gives ex2 arg = -w^2 and u^2-1 = fma(-w^2, -2ln2, -1).
__device__ float4 g_P[OUTF * INF];
__device__ float  g_Xx[INF * BATCH];    // x transposed [i][b]
__device__ float  g_Xs[INF * BATCH];    // silu(x) transposed [i][b]

// ---------------------------------------------------------------------------
__global__ void prep_params(const float* __restrict__ bw, const float* __restrict__ ww,
                            const float* __restrict__ sc, const float* __restrict__ tr) {
    int idx = blockIdx.x * blockDim.x + threadIdx.x;
    if (idx >= OUTF * INF) return;
    const float K = 0.84936056542f;          // sqrt(ln2/2)
    float inv = K * __frcp_rn(sc[idx]);
    float4 p;
    p.x = inv;
    p.y = -tr[idx] * inv;
    p.z = ww[idx];
    p.w = bw[idx];
    g_P[idx] = p;
}

// ---------------------------------------------------------------------------
__global__ void prep_x(const float* __restrict__ x) {
    int idx = blockIdx.x * blockDim.x + threadIdx.x;
    if (idx >= INF * BATCH) return;
    int i = idx >> 10;
    int b = idx & (BATCH - 1);
    float v = x[(size_t)b * INF + i];
    float e = __expf(-v);
    g_Xx[idx] = v;
    g_Xs[idx] = v / (1.0f + e);
}

// ---------------------------------------------------------------------------
// Main: 64x64 (b,o) tile, 256 threads. Micro-tile: 4 b (2 lane-pairs) x 4 o.
// f32x2 paired over batch: x/silu pairs come straight from LDS.128, no movs.
// ---------------------------------------------------------------------------
__global__ void __launch_bounds__(256)
wkan_main(const float* __restrict__ bias, float* __restrict__ out) {
    __shared__ float4     sP[2][KT][OT];        // 32 KB (swizzled cols)
    __shared__ ulonglong2 sX[2][KT][BT / 4];    //  8 KB (x pairs)
    __shared__ ulonglong2 sS[2][KT][BT / 4];    //  8 KB (silu pairs)  -> 48 KB

    const int tid = threadIdx.x;
    const int tb  = tid & 15;        // 16 batch groups (4 b = 2 pairs each)
    const int to  = tid >> 4;        // 16 o groups (4 o each)
    const int b0  = blockIdx.x * BT;
    const int o0  = blockIdx.y * OT;

    auto load_stage = [&](int s, int buf) {
        const int k0 = s * KT;
        #pragma unroll
        for (int j = 0; j < 4; ++j) {
            int idx = j * 256 + tid;
            int k   = idx & 15;
            int o   = idx >> 4;
            const float4* src = &g_P[(size_t)(o0 + o) * INF + (k0 + k)];
            uint32_t dst = (uint32_t)__cvta_generic_to_shared(&sP[buf][k][o ^ (k & 7)]);
            asm volatile("cp.async.cg.shared.global [%0], [%1], 16;\n" :: "r"(dst), "l"(src));
        }
        {
            int k  = tid >> 4;
            int b4 = tid & 15;
            const float* srcx = &g_Xx[(size_t)(k0 + k) * BATCH + b0 + b4 * 4];
            uint32_t dstx = (uint32_t)__cvta_generic_to_shared(&sX[buf][k][b4]);
            asm volatile("cp.async.cg.shared.global [%0], [%1], 16;\n" :: "r"(dstx), "l"(srcx));
            const float* srcs = &g_Xs[(size_t)(k0 + k) * BATCH + b0 + b4 * 4];
            uint32_t dsts = (uint32_t)__cvta_generic_to_shared(&sS[buf][k][b4]);
            asm volatile("cp.async.cg.shared.global [%0], [%1], 16;\n" :: "r"(dsts), "l"(srcs));
        }
        asm volatile("cp.async.commit_group;\n" ::);
    };

    const ull C2N = pk(-1.38629436112f, -1.38629436112f);   // -2*ln2
    const ull M1  = pk(-1.0f, -1.0f);
    const ull SGN = 0x8000000080000000ULL;

    ull acc[2][4];   // [b-pair][o]
    #pragma unroll
    for (int i = 0; i < 2; ++i)
        #pragma unroll
        for (int j = 0; j < 4; ++j) acc[i][j] = 0ull;

    load_stage(0, 0);
    load_stage(1, 1);

    #pragma unroll 1
    for (int s = 0; s < NSTAGES; ++s) {
        asm volatile("cp.async.wait_group 1;\n" ::);
        __syncthreads();
        const int buf = s & 1;

        #pragma unroll 8
        for (int k = 0; k < KT; ++k) {
            ulonglong2 xp = sX[buf][k][tb];   // {x_b0,x_b1},{x_b2,x_b3}
            ulonglong2 sp = sS[buf][k][tb];
            ull xx[2] = { xp.x, xp.y };
            ull ss[2] = { sp.x, sp.y };
            #pragma unroll
            for (int oo = 0; oo < 4; ++oo) {
                float4 p = sP[buf][k][(4 * to + oo) ^ (k & 7)];
                ull inv2 = pk(p.x, p.x);
                ull ty2  = pk(p.y, p.y);
                ull wz2  = pk(p.z, p.z);
                ull wb2  = pk(p.w, p.w);
                #pragma unroll
                for (int pp = 0; pp < 2; ++pp) {
                    ull w  = fma2(xx[pp], inv2, ty2);    // K*(x-t)/s, both b lanes
                    ull wn = xor64(w, SGN);              // -w (ALU pipe)
                    ull qn = mul2(w, wn);                // -w^2 = ex2 args
                    float qa, qb; upk(qa, qb, qn);
                    ull e2   = pk(ex2f(qa), ex2f(qb));   // exp(-u^2/2)
                    ull u2m1 = fma2(qn, C2N, M1);        // u^2 - 1
                    ull t    = mul2(u2m1, e2);
                    acc[pp][oo] = fma2(t, wz2, acc[pp][oo]);       // wavelet
                    acc[pp][oo] = fma2(ss[pp], wb2, acc[pp][oo]);  // base (fused)
                }
            }
        }
        __syncthreads();
        if (s + 2 < NSTAGES) load_stage(s + 2, buf);
        else                 asm volatile("cp.async.commit_group;\n" ::);
    }

    // Epilogue: thread owns b = b0+4*tb .. +3 (pairs pp), o = o0+4*to .. +3
    float4 bv = *reinterpret_cast<const float4*>(bias + o0 + 4 * to);
    #pragma unroll
    for (int pp = 0; pp < 2; ++pp) {
        float lo[4], hi[4];
        #pragma unroll
        for (int oo = 0; oo < 4; ++oo) upk(lo[oo], hi[oo], acc[pp][oo]);
        int b = b0 + 4 * tb + 2 * pp;
        float4 r0, r1;
        r0.x = lo[0] + bv.x; r0.y = lo[1] + bv.y; r0.z = lo[2] + bv.z; r0.w = lo[3] + bv.w;
        r1.x = hi[0] + bv.x; r1.y = hi[1] + bv.y; r1.z = hi[2] + bv.z; r1.w = hi[3] + bv.w;
        *reinterpret_cast<float4*>(out + (size_t)b       * OUTF + o0 + 4 * to) = r0;
        *reinterpret_cast<float4*>(out + (size_t)(b + 1) * OUTF + o0 + 4 * to) = r1;
    }
}

// ---------------------------------------------------------------------------
extern "C" void kernel_launch(void* const* d_in, const int* in_sizes, int n_in,
                              void* d_out, int out_size) {
    (void)in_sizes; (void)n_in; (void)out_size;
    const float* x    = (const float*)d_in[0];
    const float* bw   = (const float*)d_in[1];
    const float* ww   = (const float*)d_in[2];
    const float* sc   = (const float*)d_in[3];
    const float* tr   = (const float*)d_in[4];
    const float* bias = (const float*)d_in[5];
    float* out = (float*)d_out;

    prep_params<<<(OUTF * INF + 255) / 256, 256>>>(bw, ww, sc, tr);
    prep_x<<<(INF * BATCH + 255) / 256, 256>>>(x);
    wkan_main<<<dim3(BATCH / BT, OUTF / OT), 256>>>(bias, out);
}

// round 5
// speedup vs baseline: 1.3729x; 1.2002x over previous
#include <cuda_runtime.h>
#include <cstdint>

#define BATCH 1024
#define INF   512
#define OUTF  512
#define BT    64
#define OT    64
#define KT    16
#define NSTAGES   (INF / KT)     // 32
#define MAIN_S    28             // stages done by main CTAs
#define NTILES    128            // 16 b-tiles x 8 o-tiles
#define NMAIN     128
#define NEXTRA    20             // 148 - 128
#define GRID_MAIN 148

// Scratch (static __device__ globals: allocation-free per harness rules)
// Param per (o,i): float4 {inv = K/s, ty = -K*t/s, wz, wb}, K = sqrt(ln2/2):
// w = x*inv+ty  ->  ex2(-w^2) = exp(-u^2/2),  u^2-1 = fma(-w^2, -2ln2, -1)
__device__ float4 g_P[OUTF * INF];
__device__ float  g_Xx[INF * BATCH];      // x transposed [i][b]
__device__ float  g_Xs[INF * BATCH];      // silu(x) transposed [i][b]
__device__ float  g_part[BATCH * OUTF];   // partial sums (stages 28..31)

__device__ __forceinline__ float ex2f(float q) {
    float r; asm("ex2.approx.ftz.f32 %0, %1;" : "=f"(r) : "f"(q)); return r;
}

#define PBLOCKS 1024   // OUTF*INF/256
#define XBLOCKS 2048   // INF*BATCH/256

// ---------------------------------------------------------------------------
// Fused prep: blocks [0,PBLOCKS) pack params; blocks [PBLOCKS, +XBLOCKS) do x.
// ---------------------------------------------------------------------------
__global__ void prep_all(const float* __restrict__ x,
                         const float* __restrict__ bw, const float* __restrict__ ww,
                         const float* __restrict__ sc, const float* __restrict__ tr) {
    if (blockIdx.x < PBLOCKS) {
        int idx = blockIdx.x * 256 + threadIdx.x;
        const float K = 0.84936056542f;          // sqrt(ln2/2)
        float inv = K * __frcp_rn(sc[idx]);
        float4 p;
        p.x = inv;
        p.y = -tr[idx] * inv;
        p.z = ww[idx];
        p.w = bw[idx];
        g_P[idx] = p;
    } else {
        int idx = (blockIdx.x - PBLOCKS) * 256 + threadIdx.x;
        int i = idx >> 10;
        int b = idx & (BATCH - 1);
        float v = x[(size_t)b * INF + i];
        float e = __expf(-v);
        g_Xx[idx] = v;
        g_Xs[idx] = v / (1.0f + e);
    }
}

// ---------------------------------------------------------------------------
// Shared tile buffers (48 KB static)
// ---------------------------------------------------------------------------
__shared__ float4 sP[2][KT][OT];        // 32 KB (swizzled cols)
__shared__ float4 sX[2][KT][BT / 4];    //  8 KB
__shared__ float4 sS[2][KT][BT / 4];    //  8 KB

__device__ __forceinline__ void load_stage(int s, int buf, int b0, int o0, int tid) {
    const int k0 = s * KT;
    #pragma unroll
    for (int j = 0; j < 4; ++j) {
        int idx = j * 256 + tid;
        int k   = idx & 15;
        int o   = idx >> 4;
        const float4* src = &g_P[(size_t)(o0 + o) * INF + (k0 + k)];
        uint32_t dst = (uint32_t)__cvta_generic_to_shared(&sP[buf][k][o ^ (k & 7)]);
        asm volatile("cp.async.cg.shared.global [%0], [%1], 16;\n" :: "r"(dst), "l"(src));
    }
    {
        int k  = tid >> 4;
        int b4 = tid & 15;
        const float* srcx = &g_Xx[(size_t)(k0 + k) * BATCH + b0 + b4 * 4];
        uint32_t dstx = (uint32_t)__cvta_generic_to_shared(&sX[buf][k][b4]);
        asm volatile("cp.async.cg.shared.global [%0], [%1], 16;\n" :: "r"(dstx), "l"(srcx));
        const float* srcs = &g_Xs[(size_t)(k0 + k) * BATCH + b0 + b4 * 4];
        uint32_t dsts = (uint32_t)__cvta_generic_to_shared(&sS[buf][k][b4]);
        asm volatile("cp.async.cg.shared.global [%0], [%1], 16;\n" :: "r"(dsts), "l"(srcs));
    }
    asm volatile("cp.async.commit_group;\n" ::);
}

// Process stages [s_begin, s_end) of tile (b0,o0); write out or g_part.
__device__ __forceinline__ void run_tile(int b0, int o0, int s_begin, int s_end,
                                         bool to_part, const float* __restrict__ bias,
                                         float* __restrict__ out) {
    const int tid = threadIdx.x;
    const int tb  = tid & 15;        // 16 batch groups (4 b each)
    const int to  = tid >> 4;        // 16 o groups (4 o each)

    float acc[4][4];
    #pragma unroll
    for (int i = 0; i < 4; ++i)
        #pragma unroll
        for (int j = 0; j < 4; ++j) acc[i][j] = 0.0f;

    load_stage(s_begin, 0, b0, o0, tid);
    load_stage(s_begin + 1, 1, b0, o0, tid);

    const float C2N = -1.38629436112f;   // -2*ln2
    float m1 = -1.0f;                    // keep -1 in a register (FFMA-imm form)

    #pragma unroll 1
    for (int s = s_begin; s < s_end; ++s) {
        asm volatile("cp.async.wait_group 1;\n" ::);
        __syncthreads();
        const int buf = (s - s_begin) & 1;

        #pragma unroll 8
        for (int k = 0; k < KT; ++k) {
            float4 xa = sX[buf][k][tb];
            float4 xs = sS[buf][k][tb];
            float xv[4] = {xa.x, xa.y, xa.z, xa.w};
            float sv[4] = {xs.x, xs.y, xs.z, xs.w};
            #pragma unroll
            for (int oo = 0; oo < 4; ++oo) {
                float4 p = sP[buf][k][(4 * to + oo) ^ (k & 7)];
                #pragma unroll
                for (int bb = 0; bb < 4; ++bb) {
                    float w  = fmaf(xv[bb], p.x, p.y);    // K*(x-t)/s
                    float qn = w * (-w);                  // -w^2 (neg = src modifier)
                    float e  = ex2f(qn);                  // exp(-u^2/2)
                    float m  = fmaf(qn, C2N, m1);         // u^2 - 1  (FFMA-imm, rt1)
                    acc[bb][oo] = fmaf(m * e, p.z, acc[bb][oo]);   // wavelet
                    acc[bb][oo] = fmaf(sv[bb], p.w, acc[bb][oo]);  // base (fused)
                }
            }
        }
        __syncthreads();
        if (s + 2 < s_end) load_stage(s + 2, buf, b0, o0, tid);
        else               asm volatile("cp.async.commit_group;\n" ::);
    }

    if (to_part) {
        #pragma unroll
        for (int bb = 0; bb < 4; ++bb) {
            int b = b0 + 4 * tb + bb;
            float4 r;
            r.x = acc[bb][0]; r.y = acc[bb][1]; r.z = acc[bb][2]; r.w = acc[bb][3];
            *reinterpret_cast<float4*>(g_part + (size_t)b * OUTF + o0 + 4 * to) = r;
        }
    } else {
        float4 bv = *reinterpret_cast<const float4*>(bias + o0 + 4 * to);
        #pragma unroll
        for (int bb = 0; bb < 4; ++bb) {
            int b = b0 + 4 * tb + bb;
            float4 r;
            r.x = acc[bb][0] + bv.x; r.y = acc[bb][1] + bv.y;
            r.z = acc[bb][2] + bv.z; r.w = acc[bb][3] + bv.w;
            *reinterpret_cast<float4*>(out + (size_t)b * OUTF + o0 + 4 * to) = r;
        }
    }
}

// ---------------------------------------------------------------------------
// Main: 148 persistent CTAs. CTAs 0..127: tile c, stages 0..27 -> out.
// CTAs 128..147: stages 28..31 of tiles (c-128, +20, ...) -> g_part.
// ---------------------------------------------------------------------------
__global__ void __launch_bounds__(256)
wkan_main(const float* __restrict__ bias, float* __restrict__ out) {
    const int c = blockIdx.x;
    if (c < NMAIN) {
        int b0 = (c & 15) * BT;
        int o0 = (c >> 4) * OT;
        run_tile(b0, o0, 0, MAIN_S, false, bias, out);
    } else {
        for (int t = c - NMAIN; t < NTILES; t += NEXTRA) {
            int b0 = (t & 15) * BT;
            int o0 = (t >> 4) * OT;
            run_tile(b0, o0, MAIN_S, NSTAGES, true, bias, out);
            __syncthreads();   // smem reuse across tiles
        }
    }
}

// ---------------------------------------------------------------------------
__global__ void combine(float* __restrict__ out) {
    int idx = blockIdx.x * 256 + threadIdx.x;   // float4 index
    float4 o = reinterpret_cast<float4*>(out)[idx];
    float4 p = reinterpret_cast<const float4*>(g_part)[idx];
    o.x += p.x; o.y += p.y; o.z += p.z; o.w += p.w;
    reinterpret_cast<float4*>(out)[idx] = o;
}

// ---------------------------------------------------------------------------
extern "C" void kernel_launch(void* const* d_in, const int* in_sizes, int n_in,
                              void* d_out, int out_size) {
    (void)in_sizes; (void)n_in; (void)out_size;
    const float* x    = (const float*)d_in[0];
    const float* bw   = (const float*)d_in[1];
    const float* ww   = (const float*)d_in[2];
    const float* sc   = (const float*)d_in[3];
    const float* tr   = (const float*)d_in[4];
    const float* bias = (const float*)d_in[5];
    float* out = (float*)d_out;

    prep_all<<<PBLOCKS + XBLOCKS, 256>>>(x, bw, ww, sc, tr);
    wkan_main<<<GRID_MAIN, 256>>>(bias, out);
    combine<<<(BATCH * OUTF / 4) / 256, 256>>>(out);
}

// round 8
// speedup vs baseline: 1.4507x; 1.0566x over previous
#include <cuda_runtime.h>
#include <cstdint>

#define BATCH 1024
#define INF   512
#define OUTF  512
#define BT    64
#define OT    64
#define KT    16
#define NSTAGES   (INF / KT)     // 32
#define MAIN_S    28             // stages done by main CTAs
#define NTILES    128            // 16 b-tiles x 8 o-tiles
#define NMAIN     128
#define NEXTRA    20             // 148 - 128
#define GRID_MAIN 148

// Scratch (static __device__ globals: allocation-free per harness rules)
// Param per (o,i): float4 {inv = K/s, ty = -K*t/s, wz, wb}, K = sqrt(1/(2ln2)):
// w = x*inv+ty  ->  ex2(-w^2) = exp(-u^2/2);  wz*(u^2-1) = fma(-w^2, -2ln2*wz, -wz)
__device__ float4 g_P[OUTF * INF];
__device__ float  g_Xx[INF * BATCH];      // x transposed [i][b]
__device__ float  g_Xs[INF * BATCH];      // silu(x) transposed [i][b]
__device__ float  g_part[BATCH * OUTF];   // partial sums (stages 28..31)

__device__ __forceinline__ float ex2f(float q) {
    float r; asm("ex2.approx.ftz.f32 %0, %1;" : "=f"(r) : "f"(q)); return r;
}

#define PBLOCKS 1024   // OUTF*INF/256
#define TBLOCKS 512    // (INF/32) * (BATCH/32) transpose tiles

// ---------------------------------------------------------------------------
// Fused prep: blocks [0,PBLOCKS) pack params; blocks [PBLOCKS,+TBLOCKS) do a
// 32x32 smem-tiled transpose of x (+silu), coalesced on both sides.
// ---------------------------------------------------------------------------
__global__ void prep_all(const float* __restrict__ x,
                         const float* __restrict__ bw, const float* __restrict__ ww,
                         const float* __restrict__ sc, const float* __restrict__ tr) {
    if (blockIdx.x < PBLOCKS) {
        int idx = blockIdx.x * 256 + threadIdx.x;
        const float K = 0.84936056542f;          // sqrt(1/(2ln2))
        float inv = K * __frcp_rn(sc[idx]);
        float4 p;
        p.x = inv;
        p.y = -tr[idx] * inv;
        p.z = ww[idx];
        p.w = bw[idx];
        g_P[idx] = p;
    } else {
        __shared__ float tX[32][33];
        __shared__ float tS[32][33];
        int bt = blockIdx.x - PBLOCKS;           // 0..511
        int i0 = (bt & 15) * 32;                 // 16 i-tiles
        int b0 = (bt >> 4) * 32;                 // 32 b-tiles
        int tc = threadIdx.x & 31;
        int tr_ = threadIdx.x >> 5;              // 0..7
        #pragma unroll
        for (int j = 0; j < 4; ++j) {
            int r = tr_ + 8 * j;                 // b offset on read
            float v = x[(size_t)(b0 + r) * INF + i0 + tc];
            float e = __expf(-v);
            tX[r][tc] = v;
            tS[r][tc] = v / (1.0f + e);
        }
        __syncthreads();
        #pragma unroll
        for (int j = 0; j < 4; ++j) {
            int r = tr_ + 8 * j;                 // i offset on write
            g_Xx[(size_t)(i0 + r) * BATCH + b0 + tc] = tX[tc][r];
            g_Xs[(size_t)(i0 + r) * BATCH + b0 + tc] = tS[tc][r];
        }
    }
}

// ---------------------------------------------------------------------------
// Shared tile buffers (48 KB static)
// ---------------------------------------------------------------------------
__shared__ float4 sP[2][KT][OT];        // 32 KB (swizzled cols)
__shared__ float4 sX[2][KT][BT / 4];    //  8 KB
__shared__ float4 sS[2][KT][BT / 4];    //  8 KB

__device__ __forceinline__ void load_stage(int s, int buf, int b0, int o0, int tid) {
    const int k0 = s * KT;
    #pragma unroll
    for (int j = 0; j < 4; ++j) {
        int idx = j * 256 + tid;
        int k   = idx & 15;
        int o   = idx >> 4;
        const float4* src = &g_P[(size_t)(o0 + o) * INF + (k0 + k)];
        uint32_t dst = (uint32_t)__cvta_generic_to_shared(&sP[buf][k][o ^ (k & 7)]);
        asm volatile("cp.async.cg.shared.global [%0], [%1], 16;\n" :: "r"(dst), "l"(src));
    }
    {
        int k  = tid >> 4;
        int b4 = tid & 15;
        const float* srcx = &g_Xx[(size_t)(k0 + k) * BATCH + b0 + b4 * 4];
        uint32_t dstx = (uint32_t)__cvta_generic_to_shared(&sX[buf][k][b4]);
        asm volatile("cp.async.cg.shared.global [%0], [%1], 16;\n" :: "r"(dstx), "l"(srcx));
        const float* srcs = &g_Xs[(size_t)(k0 + k) * BATCH + b0 + b4 * 4];
        uint32_t dsts = (uint32_t)__cvta_generic_to_shared(&sS[buf][k][b4]);
        asm volatile("cp.async.cg.shared.global [%0], [%1], 16;\n" :: "r"(dsts), "l"(srcs));
    }
    asm volatile("cp.async.commit_group;\n" ::);
}

// Process stages [s_begin, s_end) of tile (b0,o0); write out or g_part.
__device__ __forceinline__ void run_tile(int b0, int o0, int s_begin, int s_end,
                                         bool to_part, const float* __restrict__ bias,
                                         float* __restrict__ out) {
    const int tid = threadIdx.x;
    const int tb  = tid & 15;        // 16 batch groups (4 b each)
    const int to  = tid >> 4;        // 16 o groups (4 o each)

    float acc[4][4];
    #pragma unroll
    for (int i = 0; i < 4; ++i)
        #pragma unroll
        for (int j = 0; j < 4; ++j) acc[i][j] = 0.0f;

    load_stage(s_begin, 0, b0, o0, tid);
    load_stage(s_begin + 1, 1, b0, o0, tid);

    const float C2N = -1.38629436112f;   // -2*ln2

    #pragma unroll 1
    for (int s = s_begin; s < s_end; ++s) {
        asm volatile("cp.async.wait_group 1;\n" ::);
        __syncthreads();
        const int buf = (s - s_begin) & 1;

        #pragma unroll 8
        for (int k = 0; k < KT; ++k) {
            float4 xa = sX[buf][k][tb];
            float4 xs = sS[buf][k][tb];
            float xv[4] = {xa.x, xa.y, xa.z, xa.w};
            float sv[4] = {xs.x, xs.y, xs.z, xs.w};
            #pragma unroll
            for (int oo = 0; oo < 4; ++oo) {
                float4 p = sP[buf][k][(4 * to + oo) ^ (k & 7)];
                float wzC = p.z * C2N;               // -2ln2*wz (hoisted, /4 elems)
                #pragma unroll
                for (int bb = 0; bb < 4; ++bb) {
                    float w  = fmaf(xv[bb], p.x, p.y);     // K*(x-t)/s
                    float qn = w * (-w);                   // -w^2 (free src neg)
                    float e  = ex2f(qn);                   // exp(-u^2/2)
                    float mp = fmaf(qn, wzC, -p.z);        // wz*(u^2-1), free c-neg
                    acc[bb][oo] = fmaf(mp, e, acc[bb][oo]);      // wavelet
                    acc[bb][oo] = fmaf(sv[bb], p.w, acc[bb][oo]);// base (fused)
                }
            }
        }
        __syncthreads();
        if (s + 2 < s_end) load_stage(s + 2, buf, b0, o0, tid);
        else               asm volatile("cp.async.commit_group;\n" ::);
    }

    if (to_part) {
        #pragma unroll
        for (int bb = 0; bb < 4; ++bb) {
            int b = b0 + 4 * tb + bb;
            float4 r;
            r.x = acc[bb][0]; r.y = acc[bb][1]; r.z = acc[bb][2]; r.w = acc[bb][3];
            *reinterpret_cast<float4*>(g_part + (size_t)b * OUTF + o0 + 4 * to) = r;
        }
    } else {
        float4 bv = *reinterpret_cast<const float4*>(bias + o0 + 4 * to);
        #pragma unroll
        for (int bb = 0; bb < 4; ++bb) {
            int b = b0 + 4 * tb + bb;
            float4 r;
            r.x = acc[bb][0] + bv.x; r.y = acc[bb][1] + bv.y;
            r.z = acc[bb][2] + bv.z; r.w = acc[bb][3] + bv.w;
            *reinterpret_cast<float4*>(out + (size_t)b * OUTF + o0 + 4 * to) = r;
        }
    }
}

// ---------------------------------------------------------------------------
// Main: 148 persistent CTAs. CTAs 0..127: tile c, stages 0..27 -> out.
// CTAs 128..147: stages 28..31 of 6-7 tiles each -> g_part.
// ---------------------------------------------------------------------------
__global__ void __launch_bounds__(256)
wkan_main(const float* __restrict__ bias, float* __restrict__ out) {
    const int c = blockIdx.x;
    if (c < NMAIN) {
        int b0 = (c & 15) * BT;
        int o0 = (c >> 4) * OT;
        run_tile(b0, o0, 0, MAIN_S, false, bias, out);
    } else {
        for (int t = c - NMAIN; t < NTILES; t += NEXTRA) {
            int b0 = (t & 15) * BT;
            int o0 = (t >> 4) * OT;
            run_tile(b0, o0, MAIN_S, NSTAGES, true, bias, out);
            __syncthreads();   // smem reuse across tiles
        }
    }
}

// ---------------------------------------------------------------------------
__global__ void combine(float* __restrict__ out) {
    int idx = blockIdx.x * 256 + threadIdx.x;   // float4 index
    float4 o = reinterpret_cast<float4*>(out)[idx];
    float4 p = reinterpret_cast<const float4*>(g_part)[idx];
    o.x += p.x; o.y += p.y; o.z += p.z; o.w += p.w;
    reinterpret_cast<float4*>(out)[idx] = o;
}

// ---------------------------------------------------------------------------
extern "C" void kernel_launch(void* const* d_in, const int* in_sizes, int n_in,
                              void* d_out, int out_size) {
    (void)in_sizes; (void)n_in; (void)out_size;
    const float* x    = (const float*)d_in[0];
    const float* bw   = (const float*)d_in[1];
    const float* ww   = (const float*)d_in[2];
    const float* sc   = (const float*)d_in[3];
    const float* tr   = (const float*)d_in[4];
    const float* bias = (const float*)d_in[5];
    float* out = (float*)d_out;

    prep_all<<<PBLOCKS + TBLOCKS, 256>>>(x, bw, ww, sc, tr);
    wkan_main<<<GRID_MAIN, 256>>>(bias, out);
    combine<<<(BATCH * OUTF / 4) / 256, 256>>>(out);
}